// round 5
// baseline (speedup 1.0000x reference)
#include <cuda_runtime.h>
#include <cuda_bf16.h>
#include <cstdint>

// Problem constants
#define TT 16
#define NN 20000
#define EE 320000
#define HH 128
#define H3 384
#define PP 100000

// ---------------- device scratch (no cudaMalloc allowed) ----------------
__device__ float g_bufA[TT * NN * HH];      // 163.8 MB
__device__ float g_bufB[TT * NN * HH];      // 163.8 MB
__device__ float g_GI[TT * NN * H3];        // 491.5 MB
__device__ float g_GH[NN * H3];             // 30.7 MB
__device__ float g_hA[NN * HH];             // 10.2 MB
__device__ float g_hB[NN * HH];             // 10.2 MB
__device__ float g_dinv[TT * NN];
__device__ float g_csr_w[TT * EE];
__device__ int   g_csr_src[TT * EE];
__device__ int   g_rowptr[TT * (NN + 1)];
__device__ int   g_cnt[TT * NN];
__device__ int   g_cnt2[TT * NN];
__device__ float g_wT[2][HH * H3];          // 0: w_ih^T [128][384], 1: w_hh^T

__device__ __forceinline__ float* selbuf(int s) {
    switch (s) {
        case 0: return g_bufA;
        case 1: return g_bufB;
        case 2: return g_GI;
        case 3: return g_GH;
        case 4: return g_hA;
        case 5: return g_hB;
        case 6: return g_wT[0];
        case 7: return g_wT[1];
    }
    return nullptr;
}

// ---------------- CSR build ----------------
__global__ void k_zero_counts() {
    int i = blockIdx.x * blockDim.x + threadIdx.x;
    if (i < TT * NN) { g_cnt[i] = 0; g_cnt2[i] = 0; }
}

__global__ void k_hist(const int* __restrict__ ei) {
    int idx = blockIdx.x * blockDim.x + threadIdx.x;
    if (idx >= TT * EE) return;
    int t = idx / EE;
    int e = idx - t * EE;
    int d = ei[(size_t)t * 2 * EE + EE + e];
    atomicAdd(&g_cnt[t * NN + d], 1);
}

__global__ void k_dinv() {
    int i = blockIdx.x * blockDim.x + threadIdx.x;
    if (i < TT * NN) g_dinv[i] = rsqrtf((float)g_cnt[i] + 1.0f);
}

// one block per frame; 1024 threads; exclusive scan of 20000 counts
__global__ void k_scan() {
    int t = blockIdx.x;
    __shared__ int s_part[1024];
    const int chunk = (NN + 1023) / 1024;   // 20
    int base = threadIdx.x * chunk;
    int sum = 0;
    for (int i = 0; i < chunk; i++) {
        int idx = base + i;
        if (idx < NN) sum += g_cnt[t * NN + idx];
    }
    s_part[threadIdx.x] = sum;
    __syncthreads();
    if (threadIdx.x == 0) {
        int acc = 0;
        for (int i = 0; i < 1024; i++) { int v = s_part[i]; s_part[i] = acc; acc += v; }
        g_rowptr[t * (NN + 1) + NN] = acc;
    }
    __syncthreads();
    int acc = s_part[threadIdx.x];
    for (int i = 0; i < chunk; i++) {
        int idx = base + i;
        if (idx < NN) {
            g_rowptr[t * (NN + 1) + idx] = acc;
            acc += g_cnt[t * NN + idx];
        }
    }
}

__global__ void k_scatter(const int* __restrict__ ei) {
    int idx = blockIdx.x * blockDim.x + threadIdx.x;
    if (idx >= TT * EE) return;
    int t = idx / EE;
    int e = idx - t * EE;
    int s = ei[(size_t)t * 2 * EE + e];
    int d = ei[(size_t)t * 2 * EE + EE + e];
    int pos = g_rowptr[t * (NN + 1) + d] + atomicAdd(&g_cnt2[t * NN + d], 1);
    g_csr_src[(size_t)t * EE + pos] = s;
    g_csr_w[(size_t)t * EE + pos] = g_dinv[t * NN + s] * g_dinv[t * NN + d];
}

__global__ void k_transpose(const float* __restrict__ wih, const float* __restrict__ whh) {
    int idx = blockIdx.x * blockDim.x + threadIdx.x;
    if (idx >= 2 * H3 * HH) return;
    int which = idx / (H3 * HH);
    int r = idx - which * (H3 * HH);
    int n = r / HH;      // 0..383 (rows of w)
    int k = r - n * HH;  // 0..127
    const float* w = which ? whh : wih;
    g_wT[which][k * H3 + n] = w[n * HH + k];
}

// ---------------- GEMM: C[MxNC] = A[Mx128] * B[128xNC] (+bias) ----------------
// block 256 threads, tile 128x128, K=128 in 4 k-tiles of 32
__device__ __forceinline__ void ffma2(unsigned long long& acc, unsigned long long a,
                                      unsigned long long b) {
    asm("fma.rn.f32x2 %0, %1, %2, %0;" : "+l"(acc) : "l"(a), "l"(b));
}

__global__ __launch_bounds__(256, 2) void gemm_k(
    const float* __restrict__ Aext, int Asel,
    const float* __restrict__ Bext, int Bsel,
    const float* __restrict__ bias, int Csel,
    int M, int NC)
{
    __shared__ float As[32][132];   // [k][m], padded (528B rows, 16B aligned)
    __shared__ float Bs[32][128];   // [k][n]

    const float* A = Aext ? Aext : selbuf(Asel);
    const float* B = Bext ? Bext : selbuf(Bsel);
    float* C = selbuf(Csel);

    int m0 = blockIdx.x * 128;
    int n0 = blockIdx.y * 128;
    int tid = threadIdx.x;
    int tm = (tid >> 4) * 8;   // 0..120
    int tn = (tid & 15) * 8;   // 0..120

    int lk = tid & 31;         // A load: k within k-tile
    int lmb = tid >> 5;        // A load: base row 0..7
    int bf = tid & 31;         // B load: float4 column 0..31
    int kb = tid >> 5;         // B load: base k 0..7

    unsigned long long acc[8][4];
#pragma unroll
    for (int i = 0; i < 8; i++)
#pragma unroll
        for (int j = 0; j < 4; j++) acc[i][j] = 0ULL;

    for (int kt = 0; kt < 128; kt += 32) {
#pragma unroll
        for (int i = 0; i < 16; i++) {
            int m = m0 + lmb + i * 8;
            float v = (m < M) ? A[(size_t)m * HH + kt + lk] : 0.0f;
            As[lk][lmb + i * 8] = v;
        }
#pragma unroll
        for (int i = 0; i < 4; i++) {
            int k = kb + i * 8;
            float4 v = *(const float4*)(B + (size_t)(kt + k) * NC + n0 + bf * 4);
            *(float4*)&Bs[k][bf * 4] = v;
        }
        __syncthreads();
#pragma unroll
        for (int k = 0; k < 32; k++) {
            float4 a0 = *(const float4*)&As[k][tm];
            float4 a1 = *(const float4*)&As[k][tm + 4];
            ulonglong2 b01 = *(const ulonglong2*)&Bs[k][tn];
            ulonglong2 b23 = *(const ulonglong2*)&Bs[k][tn + 4];
            float av[8] = {a0.x, a0.y, a0.z, a0.w, a1.x, a1.y, a1.z, a1.w};
#pragma unroll
            for (int i = 0; i < 8; i++) {
                unsigned long long ad;
                asm("mov.b64 %0, {%1, %2};" : "=l"(ad) : "f"(av[i]), "f"(av[i]));
                ffma2(acc[i][0], ad, b01.x);
                ffma2(acc[i][1], ad, b01.y);
                ffma2(acc[i][2], ad, b23.x);
                ffma2(acc[i][3], ad, b23.y);
            }
        }
        __syncthreads();
    }

#pragma unroll
    for (int i = 0; i < 8; i++) {
        int m = m0 + tm + i;
        if (m < M) {
            float o[8];
#pragma unroll
            for (int j = 0; j < 4; j++) {
                float lo, hi;
                asm("mov.b64 {%0, %1}, %2;" : "=f"(lo), "=f"(hi) : "l"(acc[i][j]));
                o[2 * j] = lo; o[2 * j + 1] = hi;
            }
            if (bias) {
#pragma unroll
                for (int j = 0; j < 8; j++) o[j] += __ldg(&bias[n0 + tn + j]);
            }
            float* cp = C + (size_t)m * NC + n0 + tn;
            *(float4*)cp = make_float4(o[0], o[1], o[2], o[3]);
            *(float4*)(cp + 4) = make_float4(o[4], o[5], o[6], o[7]);
        }
    }
}

// ---------------- GCN aggregation: one warp per (frame, dst) ----------------
__global__ void k_agg(int insel, int outsel, const float* __restrict__ bias, int relu) {
    int gw = (blockIdx.x * blockDim.x + threadIdx.x) >> 5;
    int lane = threadIdx.x & 31;
    if (gw >= TT * NN) return;
    int t = gw / NN;
    int d = gw - t * NN;

    const float4* tp = (const float4*)(selbuf(insel) + (size_t)t * NN * HH);
    float4* op = (float4*)(selbuf(outsel) + (size_t)t * NN * HH);

    int base = t * (NN + 1);
    int beg = g_rowptr[base + d];
    int end = g_rowptr[base + d + 1];
    float di = g_dinv[t * NN + d];
    float sw = di * di;

    float4 acc = tp[(size_t)d * 32 + lane];
    acc.x *= sw; acc.y *= sw; acc.z *= sw; acc.w *= sw;

    const int* __restrict__ srcp = g_csr_src + (size_t)t * EE;
    const float* __restrict__ wp = g_csr_w + (size_t)t * EE;

    int e = beg;
    for (; e + 1 < end; e += 2) {
        int s0 = srcp[e];     float w0 = wp[e];
        int s1 = srcp[e + 1]; float w1 = wp[e + 1];
        float4 v0 = tp[(size_t)s0 * 32 + lane];
        float4 v1 = tp[(size_t)s1 * 32 + lane];
        acc.x += v0.x * w0 + v1.x * w1;
        acc.y += v0.y * w0 + v1.y * w1;
        acc.z += v0.z * w0 + v1.z * w1;
        acc.w += v0.w * w0 + v1.w * w1;
    }
    if (e < end) {
        int s0 = srcp[e]; float w0 = wp[e];
        float4 v0 = tp[(size_t)s0 * 32 + lane];
        acc.x += v0.x * w0; acc.y += v0.y * w0;
        acc.z += v0.z * w0; acc.w += v0.w * w0;
    }

    float4 bb = ((const float4*)bias)[lane];
    acc.x += bb.x; acc.y += bb.y; acc.z += bb.z; acc.w += bb.w;
    if (relu) {
        acc.x = fmaxf(acc.x, 0.f); acc.y = fmaxf(acc.y, 0.f);
        acc.z = fmaxf(acc.z, 0.f); acc.w = fmaxf(acc.w, 0.f);
    }
    op[(size_t)d * 32 + lane] = acc;
}

// ---------------- GRU ----------------
__global__ void k_zero_h() {
    int i = blockIdx.x * blockDim.x + threadIdx.x;
    if (i < NN * HH) g_hA[i] = 0.0f;
}

__device__ __forceinline__ float sigm(float x) { return 1.0f / (1.0f + expf(-x)); }

__global__ void k_gru(int t, int cursel, int nxtsel) {
    int idx = blockIdx.x * blockDim.x + threadIdx.x;
    if (idx >= NN * HH) return;
    int i = idx >> 7;
    int c = idx & 127;
    const float* GIt = g_GI + (size_t)t * NN * H3 + (size_t)i * H3;
    const float* GHi = g_GH + (size_t)i * H3;
    float r = sigm(GIt[c] + GHi[c]);
    float z = sigm(GIt[128 + c] + GHi[128 + c]);
    float n = tanhf(GIt[256 + c] + r * GHi[256 + c]);
    float hp = selbuf(cursel)[idx];
    selbuf(nxtsel)[idx] = (1.0f - z) * n + z * hp;
}

// ---------------- decode: one warp per pair ----------------
__global__ void k_decode(int hsel, const int* __restrict__ pairs, float* __restrict__ out) {
    int gw = (blockIdx.x * blockDim.x + threadIdx.x) >> 5;
    int lane = threadIdx.x & 31;
    if (gw >= PP) return;
    int s = pairs[gw];
    int d = pairs[PP + gw];
    const float4* h4 = (const float4*)selbuf(hsel);
    float4 a = h4[(size_t)s * 32 + lane];
    float4 b = h4[(size_t)d * 32 + lane];
    float dot = a.x * b.x + a.y * b.y + a.z * b.z + a.w * b.w;
#pragma unroll
    for (int o = 16; o; o >>= 1) dot += __shfl_xor_sync(0xFFFFFFFFu, dot, o);
    if (lane == 0) out[gw] = dot;
}

// ---------------- host ----------------
extern "C" void kernel_launch(void* const* d_in, const int* in_sizes, int n_in,
                              void* d_out, int out_size) {
    (void)in_sizes; (void)n_in; (void)out_size;
    const float* x    = (const float*)d_in[0];
    const int*   ei   = (const int*)d_in[1];
    const int*   prs  = (const int*)d_in[2];
    const float* W1   = (const float*)d_in[3];
    const float* b1   = (const float*)d_in[4];
    const float* W2   = (const float*)d_in[5];
    const float* b2   = (const float*)d_in[6];
    const float* W3   = (const float*)d_in[7];
    const float* b3   = (const float*)d_in[8];
    const float* wih  = (const float*)d_in[9];
    const float* whh  = (const float*)d_in[10];
    const float* bih  = (const float*)d_in[11];
    const float* bhh  = (const float*)d_in[12];
    float* out = (float*)d_out;

    // CSR build (also produces deg -> dinv)
    k_zero_counts<<<(TT * NN + 255) / 256, 256>>>();
    k_hist<<<(TT * EE + 255) / 256, 256>>>(ei);
    k_dinv<<<(TT * NN + 255) / 256, 256>>>();
    k_scan<<<TT, 1024>>>();
    k_scatter<<<(TT * EE + 255) / 256, 256>>>(ei);
    k_transpose<<<(2 * H3 * HH + 255) / 256, 256>>>(wih, whh);

    const int aggGrid = (TT * NN * 32 + 255) / 256;   // one warp per (t, node)
    dim3 gBig(TT * NN / 128, 1);                      // 2500 tiles, NC=128

    // GCN layer 1..3 (all frames batched)
    gemm_k<<<gBig, 256>>>(x, -1, W1, -1, nullptr, 0, TT * NN, HH);        // bufA = X@W1
    k_agg<<<aggGrid, 256>>>(0, 1, b1, 1);                                 // bufB = relu(Â bufA + b1)
    gemm_k<<<gBig, 256>>>(nullptr, 1, W2, -1, nullptr, 0, TT * NN, HH);   // bufA
    k_agg<<<aggGrid, 256>>>(0, 1, b2, 1);                                 // bufB
    gemm_k<<<gBig, 256>>>(nullptr, 1, W3, -1, nullptr, 0, TT * NN, HH);   // bufA
    k_agg<<<aggGrid, 256>>>(0, 1, b3, 0);                                 // bufB = feats [T*N,128]

    // GI[t] = feats[t] @ w_ih^T + b_ih, all frames at once
    dim3 gGI(TT * NN / 128, 3);
    gemm_k<<<gGI, 256>>>(nullptr, 1, nullptr, 6, bih, 2, TT * NN, H3);

    // GRU recurrence
    k_zero_h<<<(NN * HH + 255) / 256, 256>>>();
    dim3 gGH((NN + 127) / 128, 3);
    int cur = 4;
    for (int t = 0; t < TT; t++) {
        gemm_k<<<gGH, 256>>>(nullptr, cur, nullptr, 7, bhh, 3, NN, H3);   // GH = h@w_hh^T + b_hh
        int nxt = 9 - cur;                                                // 4 <-> 5
        k_gru<<<(NN * HH + 255) / 256, 256>>>(t, cur, nxt);
        cur = nxt;
    }

    // decode
    k_decode<<<(PP * 32 + 255) / 256, 256>>>(cur, prs, out);
}

// round 9
// speedup vs baseline: 1.0005x; 1.0005x over previous
#include <cuda_runtime.h>
#include <cuda_bf16.h>
#include <cstdint>

// Problem constants
#define TT 16
#define NN 20000
#define EE 320000
#define HH 128
#define H3 384
#define PP 100000

// ---------------- device scratch (no cudaMalloc allowed) ----------------
__device__ float g_bufA[TT * NN * HH];      // 163.8 MB
__device__ float g_bufB[TT * NN * HH];      // 163.8 MB
__device__ float g_GI[TT * NN * H3];        // 491.5 MB
__device__ float g_GH[NN * H3];             // 30.7 MB
__device__ float g_hA[NN * HH];             // 10.2 MB
__device__ float g_hB[NN * HH];             // 10.2 MB
__device__ float g_dinv[TT * NN];
__device__ float g_csr_w[TT * EE];
__device__ int   g_csr_src[TT * EE];
__device__ int   g_rowptr[TT * (NN + 1)];
__device__ int   g_cnt[TT * NN];
__device__ int   g_cnt2[TT * NN];
__device__ float g_wT[2][HH * H3];          // 0: w_ih^T [128][384], 1: w_hh^T

__device__ __forceinline__ float* selbuf(int s) {
    switch (s) {
        case 0: return g_bufA;
        case 1: return g_bufB;
        case 2: return g_GI;
        case 3: return g_GH;
        case 4: return g_hA;
        case 5: return g_hB;
        case 6: return g_wT[0];
        case 7: return g_wT[1];
    }
    return nullptr;
}

// ---------------- CSR build ----------------
__global__ void k_zero_counts() {
    int i = blockIdx.x * blockDim.x + threadIdx.x;
    if (i < TT * NN) { g_cnt[i] = 0; g_cnt2[i] = 0; }
}

__global__ void k_hist(const int* __restrict__ ei) {
    int idx = blockIdx.x * blockDim.x + threadIdx.x;
    if (idx >= TT * EE) return;
    int t = idx / EE;
    int e = idx - t * EE;
    int d = ei[(size_t)t * 2 * EE + EE + e];
    atomicAdd(&g_cnt[t * NN + d], 1);
}

__global__ void k_dinv() {
    int i = blockIdx.x * blockDim.x + threadIdx.x;
    if (i < TT * NN) g_dinv[i] = rsqrtf((float)g_cnt[i] + 1.0f);
}

// one block per frame; 1024 threads; exclusive scan of 20000 counts
__global__ void k_scan() {
    int t = blockIdx.x;
    __shared__ int s_part[1024];
    const int chunk = (NN + 1023) / 1024;   // 20
    int base = threadIdx.x * chunk;
    int sum = 0;
    for (int i = 0; i < chunk; i++) {
        int idx = base + i;
        if (idx < NN) sum += g_cnt[t * NN + idx];
    }
    s_part[threadIdx.x] = sum;
    __syncthreads();
    if (threadIdx.x == 0) {
        int acc = 0;
        for (int i = 0; i < 1024; i++) { int v = s_part[i]; s_part[i] = acc; acc += v; }
        g_rowptr[t * (NN + 1) + NN] = acc;
    }
    __syncthreads();
    int acc = s_part[threadIdx.x];
    for (int i = 0; i < chunk; i++) {
        int idx = base + i;
        if (idx < NN) {
            g_rowptr[t * (NN + 1) + idx] = acc;
            acc += g_cnt[t * NN + idx];
        }
    }
}

__global__ void k_scatter(const int* __restrict__ ei) {
    int idx = blockIdx.x * blockDim.x + threadIdx.x;
    if (idx >= TT * EE) return;
    int t = idx / EE;
    int e = idx - t * EE;
    int s = ei[(size_t)t * 2 * EE + e];
    int d = ei[(size_t)t * 2 * EE + EE + e];
    int pos = g_rowptr[t * (NN + 1) + d] + atomicAdd(&g_cnt2[t * NN + d], 1);
    g_csr_src[(size_t)t * EE + pos] = s;
    g_csr_w[(size_t)t * EE + pos] = g_dinv[t * NN + s] * g_dinv[t * NN + d];
}

__global__ void k_transpose(const float* __restrict__ wih, const float* __restrict__ whh) {
    int idx = blockIdx.x * blockDim.x + threadIdx.x;
    if (idx >= 2 * H3 * HH) return;
    int which = idx / (H3 * HH);
    int r = idx - which * (H3 * HH);
    int n = r / HH;      // 0..383 (rows of w)
    int k = r - n * HH;  // 0..127
    const float* w = which ? whh : wih;
    g_wT[which][k * H3 + n] = w[n * HH + k];
}

// ---------------- GEMM: C[MxNC] = A[Mx128] * B[128xNC] (+bias) ----------------
// block 256 threads, tile 128x128, K=128 in 4 k-tiles of 32
__device__ __forceinline__ void ffma2(unsigned long long& acc, unsigned long long a,
                                      unsigned long long b) {
    asm("fma.rn.f32x2 %0, %1, %2, %0;" : "+l"(acc) : "l"(a), "l"(b));
}

__global__ __launch_bounds__(256, 2) void gemm_k(
    const float* __restrict__ Aext, int Asel,
    const float* __restrict__ Bext, int Bsel,
    const float* __restrict__ bias, int Csel,
    int M, int NC)
{
    __shared__ float As[32][132];   // [k][m], padded (528B rows, 16B aligned)
    __shared__ float Bs[32][128];   // [k][n]

    const float* A = Aext ? Aext : selbuf(Asel);
    const float* B = Bext ? Bext : selbuf(Bsel);
    float* C = selbuf(Csel);

    int m0 = blockIdx.x * 128;
    int n0 = blockIdx.y * 128;
    int tid = threadIdx.x;
    int tm = (tid >> 4) * 8;   // 0..120
    int tn = (tid & 15) * 8;   // 0..120

    int lk = tid & 31;         // A load: k within k-tile
    int lmb = tid >> 5;        // A load: base row 0..7
    int bf = tid & 31;         // B load: float4 column 0..31
    int kb = tid >> 5;         // B load: base k 0..7

    unsigned long long acc[8][4];
#pragma unroll
    for (int i = 0; i < 8; i++)
#pragma unroll
        for (int j = 0; j < 4; j++) acc[i][j] = 0ULL;

    for (int kt = 0; kt < 128; kt += 32) {
#pragma unroll
        for (int i = 0; i < 16; i++) {
            int m = m0 + lmb + i * 8;
            float v = (m < M) ? A[(size_t)m * HH + kt + lk] : 0.0f;
            As[lk][lmb + i * 8] = v;
        }
#pragma unroll
        for (int i = 0; i < 4; i++) {
            int k = kb + i * 8;
            float4 v = *(const float4*)(B + (size_t)(kt + k) * NC + n0 + bf * 4);
            *(float4*)&Bs[k][bf * 4] = v;
        }
        __syncthreads();
#pragma unroll
        for (int k = 0; k < 32; k++) {
            float4 a0 = *(const float4*)&As[k][tm];
            float4 a1 = *(const float4*)&As[k][tm + 4];
            ulonglong2 b01 = *(const ulonglong2*)&Bs[k][tn];
            ulonglong2 b23 = *(const ulonglong2*)&Bs[k][tn + 4];
            float av[8] = {a0.x, a0.y, a0.z, a0.w, a1.x, a1.y, a1.z, a1.w};
#pragma unroll
            for (int i = 0; i < 8; i++) {
                unsigned long long ad;
                asm("mov.b64 %0, {%1, %2};" : "=l"(ad) : "f"(av[i]), "f"(av[i]));
                ffma2(acc[i][0], ad, b01.x);
                ffma2(acc[i][1], ad, b01.y);
                ffma2(acc[i][2], ad, b23.x);
                ffma2(acc[i][3], ad, b23.y);
            }
        }
        __syncthreads();
    }

#pragma unroll
    for (int i = 0; i < 8; i++) {
        int m = m0 + tm + i;
        if (m < M) {
            float o[8];
#pragma unroll
            for (int j = 0; j < 4; j++) {
                float lo, hi;
                asm("mov.b64 {%0, %1}, %2;" : "=f"(lo), "=f"(hi) : "l"(acc[i][j]));
                o[2 * j] = lo; o[2 * j + 1] = hi;
            }
            if (bias) {
#pragma unroll
                for (int j = 0; j < 8; j++) o[j] += __ldg(&bias[n0 + tn + j]);
            }
            float* cp = C + (size_t)m * NC + n0 + tn;
            *(float4*)cp = make_float4(o[0], o[1], o[2], o[3]);
            *(float4*)(cp + 4) = make_float4(o[4], o[5], o[6], o[7]);
        }
    }
}

// ---------------- GCN aggregation: one warp per (frame, dst) ----------------
__global__ void k_agg(int insel, int outsel, const float* __restrict__ bias, int relu) {
    int gw = (blockIdx.x * blockDim.x + threadIdx.x) >> 5;
    int lane = threadIdx.x & 31;
    if (gw >= TT * NN) return;
    int t = gw / NN;
    int d = gw - t * NN;

    const float4* tp = (const float4*)(selbuf(insel) + (size_t)t * NN * HH);
    float4* op = (float4*)(selbuf(outsel) + (size_t)t * NN * HH);

    int base = t * (NN + 1);
    int beg = g_rowptr[base + d];
    int end = g_rowptr[base + d + 1];
    float di = g_dinv[t * NN + d];
    float sw = di * di;

    float4 acc = tp[(size_t)d * 32 + lane];
    acc.x *= sw; acc.y *= sw; acc.z *= sw; acc.w *= sw;

    const int* __restrict__ srcp = g_csr_src + (size_t)t * EE;
    const float* __restrict__ wp = g_csr_w + (size_t)t * EE;

    int e = beg;
    for (; e + 1 < end; e += 2) {
        int s0 = srcp[e];     float w0 = wp[e];
        int s1 = srcp[e + 1]; float w1 = wp[e + 1];
        float4 v0 = tp[(size_t)s0 * 32 + lane];
        float4 v1 = tp[(size_t)s1 * 32 + lane];
        acc.x += v0.x * w0 + v1.x * w1;
        acc.y += v0.y * w0 + v1.y * w1;
        acc.z += v0.z * w0 + v1.z * w1;
        acc.w += v0.w * w0 + v1.w * w1;
    }
    if (e < end) {
        int s0 = srcp[e]; float w0 = wp[e];
        float4 v0 = tp[(size_t)s0 * 32 + lane];
        acc.x += v0.x * w0; acc.y += v0.y * w0;
        acc.z += v0.z * w0; acc.w += v0.w * w0;
    }

    float4 bb = ((const float4*)bias)[lane];
    acc.x += bb.x; acc.y += bb.y; acc.z += bb.z; acc.w += bb.w;
    if (relu) {
        acc.x = fmaxf(acc.x, 0.f); acc.y = fmaxf(acc.y, 0.f);
        acc.z = fmaxf(acc.z, 0.f); acc.w = fmaxf(acc.w, 0.f);
    }
    op[(size_t)d * 32 + lane] = acc;
}

// ---------------- GRU ----------------
__global__ void k_zero_h() {
    int i = blockIdx.x * blockDim.x + threadIdx.x;
    if (i < NN * HH) g_hA[i] = 0.0f;
}

__device__ __forceinline__ float sigm(float x) { return 1.0f / (1.0f + expf(-x)); }

__global__ void k_gru(int t, int cursel, int nxtsel) {
    int idx = blockIdx.x * blockDim.x + threadIdx.x;
    if (idx >= NN * HH) return;
    int i = idx >> 7;
    int c = idx & 127;
    const float* GIt = g_GI + (size_t)t * NN * H3 + (size_t)i * H3;
    const float* GHi = g_GH + (size_t)i * H3;
    float r = sigm(GIt[c] + GHi[c]);
    float z = sigm(GIt[128 + c] + GHi[128 + c]);
    float n = tanhf(GIt[256 + c] + r * GHi[256 + c]);
    float hp = selbuf(cursel)[idx];
    selbuf(nxtsel)[idx] = (1.0f - z) * n + z * hp;
}

// ---------------- decode: one warp per pair ----------------
__global__ void k_decode(int hsel, const int* __restrict__ pairs, float* __restrict__ out) {
    int gw = (blockIdx.x * blockDim.x + threadIdx.x) >> 5;
    int lane = threadIdx.x & 31;
    if (gw >= PP) return;
    int s = pairs[gw];
    int d = pairs[PP + gw];
    const float4* h4 = (const float4*)selbuf(hsel);
    float4 a = h4[(size_t)s * 32 + lane];
    float4 b = h4[(size_t)d * 32 + lane];
    float dot = a.x * b.x + a.y * b.y + a.z * b.z + a.w * b.w;
#pragma unroll
    for (int o = 16; o; o >>= 1) dot += __shfl_xor_sync(0xFFFFFFFFu, dot, o);
    if (lane == 0) out[gw] = dot;
}

// ---------------- host ----------------
extern "C" void kernel_launch(void* const* d_in, const int* in_sizes, int n_in,
                              void* d_out, int out_size) {
    (void)in_sizes; (void)n_in; (void)out_size;
    const float* x    = (const float*)d_in[0];
    const int*   ei   = (const int*)d_in[1];
    const int*   prs  = (const int*)d_in[2];
    const float* W1   = (const float*)d_in[3];
    const float* b1   = (const float*)d_in[4];
    const float* W2   = (const float*)d_in[5];
    const float* b2   = (const float*)d_in[6];
    const float* W3   = (const float*)d_in[7];
    const float* b3   = (const float*)d_in[8];
    const float* wih  = (const float*)d_in[9];
    const float* whh  = (const float*)d_in[10];
    const float* bih  = (const float*)d_in[11];
    const float* bhh  = (const float*)d_in[12];
    float* out = (float*)d_out;

    // CSR build (also produces deg -> dinv)
    k_zero_counts<<<(TT * NN + 255) / 256, 256>>>();
    k_hist<<<(TT * EE + 255) / 256, 256>>>(ei);
    k_dinv<<<(TT * NN + 255) / 256, 256>>>();
    k_scan<<<TT, 1024>>>();
    k_scatter<<<(TT * EE + 255) / 256, 256>>>(ei);
    k_transpose<<<(2 * H3 * HH + 255) / 256, 256>>>(wih, whh);

    const int aggGrid = (TT * NN * 32 + 255) / 256;   // one warp per (t, node)
    dim3 gBig(TT * NN / 128, 1);                      // 2500 tiles, NC=128

    // GCN layer 1..3 (all frames batched)
    gemm_k<<<gBig, 256>>>(x, -1, W1, -1, nullptr, 0, TT * NN, HH);        // bufA = X@W1
    k_agg<<<aggGrid, 256>>>(0, 1, b1, 1);                                 // bufB = relu(Â bufA + b1)
    gemm_k<<<gBig, 256>>>(nullptr, 1, W2, -1, nullptr, 0, TT * NN, HH);   // bufA
    k_agg<<<aggGrid, 256>>>(0, 1, b2, 1);                                 // bufB
    gemm_k<<<gBig, 256>>>(nullptr, 1, W3, -1, nullptr, 0, TT * NN, HH);   // bufA
    k_agg<<<aggGrid, 256>>>(0, 1, b3, 0);                                 // bufB = feats [T*N,128]

    // GI[t] = feats[t] @ w_ih^T + b_ih, all frames at once
    dim3 gGI(TT * NN / 128, 3);
    gemm_k<<<gGI, 256>>>(nullptr, 1, nullptr, 6, bih, 2, TT * NN, H3);

    // GRU recurrence
    k_zero_h<<<(NN * HH + 255) / 256, 256>>>();
    dim3 gGH((NN + 127) / 128, 3);
    int cur = 4;
    for (int t = 0; t < TT; t++) {
        gemm_k<<<gGH, 256>>>(nullptr, cur, nullptr, 7, bhh, 3, NN, H3);   // GH = h@w_hh^T + b_hh
        int nxt = 9 - cur;                                                // 4 <-> 5
        k_gru<<<(NN * HH + 255) / 256, 256>>>(t, cur, nxt);
        cur = nxt;
    }

    // decode
    k_decode<<<(PP * 32 + 255) / 256, 256>>>(cur, prs, out);
}